// round 2
// baseline (speedup 1.0000x reference)
#include <cuda_runtime.h>
#include <math.h>

#define S_N 256
#define Q_N 4096
#define T_N 8
#define D_N 1024
#define K_N 64
#define QK (Q_N * K_N)     /* 262144 */
#define EPSN 1e-12f

// ---------------- scratch (device globals; no allocations allowed) ----------------
__device__ float g_protoSum[K_N * T_N * D_N];   // class sums -> means (in place)
__device__ float g_counts[K_N];
__device__ float g_protoN[K_N * T_N * D_N];     // normalized prototypes [512][1024]
__device__ float g_protoSegN[K_N * 3 * D_N];    // normalized segment prototypes [192][1024]
__device__ float g_tsegN[Q_N * 3 * D_N];        // normalized target segments [12288][1024]
__device__ float g_invA[Q_N * T_N];             // 1/||target row||

// ---------------- helpers ----------------
__device__ __forceinline__ float blockReduceSum256(float v) {
    __shared__ float sh[8];
    const int lane = threadIdx.x & 31, wid = threadIdx.x >> 5;
#pragma unroll
    for (int o = 16; o; o >>= 1) v += __shfl_xor_sync(0xffffffffu, v, o);
    if (lane == 0) sh[wid] = v;
    __syncthreads();
    if (wid == 0) {
        float r = (lane < 8) ? sh[lane] : 0.f;
#pragma unroll
        for (int o = 4; o; o >>= 1) r += __shfl_xor_sync(0xffffffffu, r, o);
        if (lane == 0) sh[0] = r;
    }
    __syncthreads();
    return sh[0];
}

// ---------------- 1. per-class sums (deterministic scan, no atomics) ----------------
// grid: 64 classes * 32 chunks, 256 threads. Each thread owns one (t,d) slot of one class.
__global__ void proto_sum_kernel(const float* __restrict__ sup, const int* __restrict__ labels) {
    const int k = blockIdx.x >> 5;
    const int off = (blockIdx.x & 31) * 256 + threadIdx.x;  // 0..8191 within [T*D]
    float acc = 0.f, cnt = 0.f;
    for (int s = 0; s < S_N; ++s) {
        if (labels[s] == k) { acc += sup[s * (T_N * D_N) + off]; cnt += 1.f; }
    }
    g_protoSum[k * (T_N * D_N) + off] = acc;
    if (off == 0) g_counts[k] = cnt;
}

// ---------------- 2. prototype mean + L2 normalize; grid 512 blocks (k,t) ----------------
__global__ void proto_norm_kernel() {
    const int row = blockIdx.x;            // (k*8 + t)
    const int k = row >> 3;
    float4 v = ((const float4*)g_protoSum)[row * 256 + threadIdx.x];
    const float ic = 1.f / g_counts[k];
    v.x *= ic; v.y *= ic; v.z *= ic; v.w *= ic;
    const float ss = blockReduceSum256(v.x*v.x + v.y*v.y + v.z*v.z + v.w*v.w);
    const float inv = 1.f / fmaxf(sqrtf(ss), EPSN);
    ((float4*)g_protoSum)[row * 256 + threadIdx.x] = v;  // store mean (for segments)
    float4 n = make_float4(v.x*inv, v.y*inv, v.z*inv, v.w*inv);
    ((float4*)g_protoN)[row * 256 + threadIdx.x] = n;
}

// ---------------- 3. prototype segments + normalize; grid 192 blocks (k,w) ----------------
__global__ void proto_seg_kernel() {
    const int b = blockIdx.x;              // k*3 + w
    const int k = b / 3, w = b % 3;
    const int ws = w * 2;                  // window starts 0,2,4 ; length 4
    const float4* base = (const float4*)g_protoSum + (k * T_N + ws) * 256 + threadIdx.x;
    float4 v0 = base[0], v1 = base[256], v2 = base[512], v3 = base[768];
    float4 v = make_float4((v0.x+v1.x+v2.x+v3.x)*0.25f, (v0.y+v1.y+v2.y+v3.y)*0.25f,
                           (v0.z+v1.z+v2.z+v3.z)*0.25f, (v0.w+v1.w+v2.w+v3.w)*0.25f);
    const float ss = blockReduceSum256(v.x*v.x + v.y*v.y + v.z*v.z + v.w*v.w);
    const float inv = 1.f / fmaxf(sqrtf(ss), EPSN);
    float4 n = make_float4(v.x*inv, v.y*inv, v.z*inv, v.w*inv);
    ((float4*)g_protoSegN)[b * 256 + threadIdx.x] = n;
}

// ---------------- 4. target segments + normalize; grid Q*3 blocks ----------------
__global__ void tseg_kernel(const float* __restrict__ tgt) {
    const int b = blockIdx.x;              // q*3 + w
    const int q = b / 3, w = b % 3;
    const int ws = w * 2;
    const float4* base = (const float4*)tgt + (q * T_N + ws) * 256 + threadIdx.x;
    float4 v0 = base[0], v1 = base[256], v2 = base[512], v3 = base[768];
    float4 v = make_float4((v0.x+v1.x+v2.x+v3.x)*0.25f, (v0.y+v1.y+v2.y+v3.y)*0.25f,
                           (v0.z+v1.z+v2.z+v3.z)*0.25f, (v0.w+v1.w+v2.w+v3.w)*0.25f);
    const float ss = blockReduceSum256(v.x*v.x + v.y*v.y + v.z*v.z + v.w*v.w);
    const float inv = 1.f / fmaxf(sqrtf(ss), EPSN);
    float4 n = make_float4(v.x*inv, v.y*inv, v.z*inv, v.w*inv);
    ((float4*)g_tsegN)[b * 256 + threadIdx.x] = n;
}

// ---------------- 5. target frame inverse norms; grid 32768 blocks ----------------
__global__ void tnorm_kernel(const float* __restrict__ tgt) {
    const int row = blockIdx.x;            // q*8 + t
    float4 v = ((const float4*)tgt)[row * 256 + threadIdx.x];
    const float ss = blockReduceSum256(v.x*v.x + v.y*v.y + v.z*v.z + v.w*v.w);
    if (threadIdx.x == 0) g_invA[row] = 1.f / fmaxf(sqrtf(ss), EPSN);
}

// ---------------- 6. main GEMM (32768x512x1024) with fused bi-MHM epilogue ----------------
// Block: 64 M-rows (8 queries) x 256 N-rows (32 classes). 256 threads.
// Thread (qi,ki) owns the full 8x8 (tq,ts) block of one (q,class) pair.
__global__ void __launch_bounds__(256, 2)
main_gemm_kernel(const float* __restrict__ tgt, float* __restrict__ out) {
    __shared__ float4 As4[8 * 64];    // [kgroup][m_local] : 4 consecutive k per float4
    __shared__ float4 Bs4[8 * 256];   // [kgroup][n_local]
    __shared__ float invAs[64];

    const int tid = threadIdx.x;
    const int qi = tid >> 5;          // 0..7  (query within block)
    const int ki = tid & 31;          // 0..31 (class within block)
    const int m0 = blockIdx.x * 64;
    const int n0 = blockIdx.y * 256;

    if (tid < 64) invAs[tid] = g_invA[m0 + tid];
    __syncthreads();

    const int lr = tid >> 3;          // 0..31 load row
    const int lc = tid & 7;           // float4 column group

    const float s0 = invAs[lr];
    const float s1 = invAs[lr + 32];

    const float* aptr = tgt + (size_t)(m0 + lr) * D_N + lc * 4;
    const float* bptr = g_protoN + (size_t)(n0 + lr) * D_N + lc * 4;

    float acc[8][8];
#pragma unroll
    for (int i = 0; i < 8; ++i)
#pragma unroll
        for (int j = 0; j < 8; ++j) acc[i][j] = 0.f;

    for (int kb = 0; kb < D_N; kb += 32) {
        float4 a0 = *(const float4*)(aptr + kb);
        float4 a1 = *(const float4*)(aptr + 32 * D_N + kb);
        float4 bb[8];
#pragma unroll
        for (int j = 0; j < 8; ++j)
            bb[j] = *(const float4*)(bptr + (size_t)(32 * j) * D_N + kb);

        __syncthreads();  // previous compute done reading smem
        a0.x *= s0; a0.y *= s0; a0.z *= s0; a0.w *= s0;
        a1.x *= s1; a1.y *= s1; a1.z *= s1; a1.w *= s1;
        As4[lc * 64 + lr]      = a0;
        As4[lc * 64 + 32 + lr] = a1;
#pragma unroll
        for (int j = 0; j < 8; ++j)
            Bs4[lc * 256 + lr + 32 * j] = bb[j];
        __syncthreads();

#pragma unroll
        for (int kg = 0; kg < 8; ++kg) {
            float4 a[8];
#pragma unroll
            for (int tq = 0; tq < 8; ++tq) a[tq] = As4[kg * 64 + qi * 8 + tq];
#pragma unroll
            for (int ts = 0; ts < 8; ++ts) {
                float4 b = Bs4[kg * 256 + ki * 8 + ts];
#pragma unroll
                for (int tq = 0; tq < 8; ++tq) {
                    acc[tq][ts] = fmaf(a[tq].x, b.x, acc[tq][ts]);
                    acc[tq][ts] = fmaf(a[tq].y, b.y, acc[tq][ts]);
                    acc[tq][ts] = fmaf(a[tq].z, b.z, acc[tq][ts]);
                    acc[tq][ts] = fmaf(a[tq].w, b.w, acc[tq][ts]);
                }
            }
        }
    }

    // -global = sum_tq max_ts sim + sum_ts max_tq sim - 16
    float sumRow = 0.f, sumCol = 0.f;
#pragma unroll
    for (int tq = 0; tq < 8; ++tq) {
        float m = acc[tq][0];
#pragma unroll
        for (int ts = 1; ts < 8; ++ts) m = fmaxf(m, acc[tq][ts]);
        sumRow += m;
    }
#pragma unroll
    for (int ts = 0; ts < 8; ++ts) {
        float m = acc[0][ts];
#pragma unroll
        for (int tq = 1; tq < 8; ++tq) m = fmaxf(m, acc[tq][ts]);
        sumCol += m;
    }
    const int q = (m0 >> 3) + qi;
    const int c = (n0 >> 3) + ki;
    out[QK + q * K_N + c] = sumRow + sumCol - 16.0f;
}

// ---------------- 7. segment GEMM (12288x192x1024) with fused 3x3 epilogue ----------------
// Block: 48 M-rows (16 queries) x 48 N-rows (16 classes). Thread owns a 3x3 block.
__global__ void __launch_bounds__(256)
seg_gemm_kernel(float* __restrict__ out) {
    __shared__ float4 As4[8 * 48];
    __shared__ float4 Bs4[8 * 48];
    const int tid = threadIdx.x;
    const int qi = tid >> 4;          // 0..15
    const int ki = tid & 15;          // 0..15
    const int r0 = blockIdx.x * 48;
    const int c0 = blockIdx.y * 48;
    const int lr = tid >> 3;          // 0..31
    const int lc = tid & 7;

    const float* aptr = g_tsegN + (size_t)(r0 + lr) * D_N + lc * 4;
    const float* bptr = g_protoSegN + (size_t)(c0 + lr) * D_N + lc * 4;

    float acc[3][3];
#pragma unroll
    for (int i = 0; i < 3; ++i)
#pragma unroll
        for (int j = 0; j < 3; ++j) acc[i][j] = 0.f;

    for (int kb = 0; kb < D_N; kb += 32) {
        float4 a0 = *(const float4*)(aptr + kb);
        float4 b0 = *(const float4*)(bptr + kb);
        float4 a1 = make_float4(0.f,0.f,0.f,0.f), b1 = a1;
        if (tid < 128) {   // rows 32..47
            a1 = *(const float4*)(aptr + 32 * D_N + kb);
            b1 = *(const float4*)(bptr + 32 * D_N + kb);
        }
        __syncthreads();
        As4[lc * 48 + lr] = a0;
        Bs4[lc * 48 + lr] = b0;
        if (tid < 128) {
            As4[lc * 48 + 32 + lr] = a1;
            Bs4[lc * 48 + 32 + lr] = b1;
        }
        __syncthreads();

#pragma unroll
        for (int kg = 0; kg < 8; ++kg) {
            float4 a[3], b[3];
#pragma unroll
            for (int j = 0; j < 3; ++j) a[j] = As4[kg * 48 + qi * 3 + j];
#pragma unroll
            for (int j = 0; j < 3; ++j) b[j] = Bs4[kg * 48 + ki * 3 + j];
#pragma unroll
            for (int i = 0; i < 3; ++i)
#pragma unroll
                for (int j = 0; j < 3; ++j) {
                    acc[i][j] = fmaf(a[i].x, b[j].x, acc[i][j]);
                    acc[i][j] = fmaf(a[i].y, b[j].y, acc[i][j]);
                    acc[i][j] = fmaf(a[i].z, b[j].z, acc[i][j]);
                    acc[i][j] = fmaf(a[i].w, b[j].w, acc[i][j]);
                }
        }
    }

    // rows i = target segs (tq), cols j = proto segs (ts)
    float sRow = 0.f, sCol = 0.f;
#pragma unroll
    for (int i = 0; i < 3; ++i) {
        float m = fmaxf(acc[i][0], fmaxf(acc[i][1], acc[i][2]));
        sRow += m;
    }
#pragma unroll
    for (int j = 0; j < 3; ++j) {
        float m = fmaxf(acc[0][j], fmaxf(acc[1][j], acc[2][j]));
        sCol += m;
    }
    const int q = blockIdx.x * 16 + qi;
    const int c = blockIdx.y * 16 + ki;
    out[2 * QK + q * K_N + c] = sCol - 3.0f;   // -seg_s2q = sum_ts max_tq sim - 3
    out[3 * QK + q * K_N + c] = sRow - 3.0f;   // -seg_q2s = sum_tq max_ts sim - 3
}

// ---------------- 8. fusion combine ----------------
__global__ void combine_kernel(const float* __restrict__ ls, const float* __restrict__ fl,
                               float* __restrict__ out) {
    const int i = blockIdx.x * 256 + threadIdx.x;
    const float f0 = fl[0], f1 = fl[1], f2 = fl[2];
    const float mx = fmaxf(f0, fmaxf(f1, f2));
    const float e0 = expf(f0 - mx), e1 = expf(f1 - mx), e2 = expf(f2 - mx);
    const float scale = expf(ls[0]) / (e0 + e1 + e2);
    out[i] = (e0 * out[QK + i] + e1 * out[2 * QK + i] + e2 * out[3 * QK + i]) * scale;
}

// ---------------- launch ----------------
extern "C" void kernel_launch(void* const* d_in, const int* in_sizes, int n_in,
                              void* d_out, int out_size) {
    const float* sup    = (const float*)d_in[0];   // [256,8,1024]
    const float* tgt    = (const float*)d_in[1];   // [4096,8,1024]
    const int*   labels = (const int*)d_in[2];     // [256]
    const float* ls     = (const float*)d_in[3];   // scalar
    const float* fl     = (const float*)d_in[4];   // [3]
    float* out = (float*)d_out;                    // 4 * 4096 * 64

    proto_sum_kernel<<<K_N * 32, 256>>>(sup, labels);
    proto_norm_kernel<<<K_N * T_N, 256>>>();
    proto_seg_kernel<<<K_N * 3, 256>>>();
    tseg_kernel<<<Q_N * 3, 256>>>(tgt);
    tnorm_kernel<<<Q_N * T_N, 256>>>(tgt);
    main_gemm_kernel<<<dim3(Q_N * T_N / 64, 2), 256>>>(tgt, out);
    seg_gemm_kernel<<<dim3(Q_N * 3 / 48, K_N * 3 / 48), 256>>>(out);
    combine_kernel<<<QK / 256, 256>>>(ls, fl, out);
}

// round 4
// speedup vs baseline: 9.6860x; 9.6860x over previous
#include <cuda_runtime.h>
#include <cuda_bf16.h>
#include <math.h>
#include <stdint.h>

#define S_N 256
#define Q_N 4096
#define T_N 8
#define D_N 1024
#define K_N 64
#define QK (Q_N * K_N)     /* 262144 */
#define EPSN 1e-12f
#define P_SM 132           /* sim buffer row pitch (floats) */

// ---------------- scratch (device globals; no allocations allowed) ----------------
__device__ float g_protoSum[K_N * T_N * D_N];   // class sums -> means (in place)
__device__ float g_counts[K_N];
__device__ __align__(16) __nv_bfloat16 g_protoNb[K_N * T_N * D_N];     // normalized prototypes [512][1024]
__device__ __align__(16) __nv_bfloat16 g_protoSegNb[K_N * 4 * D_N];    // normalized seg protos, padded [256][1024]
__device__ __align__(16) __nv_bfloat16 g_tgtNb[Q_N * T_N * D_N];       // normalized target frames [32768][1024]
__device__ __align__(16) __nv_bfloat16 g_tsegNb[Q_N * 4 * D_N];        // normalized target segs, padded [16384][1024]

// ---------------- helpers ----------------
__device__ __forceinline__ float blockReduceSum256(float v) {
    __shared__ float sh[8];
    const int lane = threadIdx.x & 31, wid = threadIdx.x >> 5;
#pragma unroll
    for (int o = 16; o; o >>= 1) v += __shfl_xor_sync(0xffffffffu, v, o);
    if (lane == 0) sh[wid] = v;
    __syncthreads();
    if (wid == 0) {
        float r = (lane < 8) ? sh[lane] : 0.f;
#pragma unroll
        for (int o = 4; o; o >>= 1) r += __shfl_xor_sync(0xffffffffu, r, o);
        if (lane == 0) sh[0] = r;
    }
    __syncthreads();
    return sh[0];
}

__device__ __forceinline__ float warpReduceSum(float v) {
#pragma unroll
    for (int o = 16; o; o >>= 1) v += __shfl_xor_sync(0xffffffffu, v, o);
    return v;
}

// ---------------- 1. per-class sums (deterministic scan, no atomics) ----------------
__global__ void proto_sum_kernel(const float* __restrict__ sup, const int* __restrict__ labels) {
    const int k = blockIdx.x >> 5;
    const int off = (blockIdx.x & 31) * 256 + threadIdx.x;  // 0..8191 within [T*D]
    float acc = 0.f, cnt = 0.f;
    for (int s = 0; s < S_N; ++s) {
        if (labels[s] == k) { acc += sup[s * (T_N * D_N) + off]; cnt += 1.f; }
    }
    g_protoSum[k * (T_N * D_N) + off] = acc;
    if (off == 0) g_counts[k] = cnt;
}

// ---------------- 2. prototype mean + L2 normalize -> bf16; grid 512 ----------------
__global__ void proto_norm_kernel() {
    const int row = blockIdx.x;            // (k*8 + t)
    const int k = row >> 3;
    float4 v = ((const float4*)g_protoSum)[row * 256 + threadIdx.x];
    const float ic = 1.f / g_counts[k];
    v.x *= ic; v.y *= ic; v.z *= ic; v.w *= ic;
    const float ss = blockReduceSum256(v.x*v.x + v.y*v.y + v.z*v.z + v.w*v.w);
    const float inv = 1.f / fmaxf(sqrtf(ss), EPSN);
    ((float4*)g_protoSum)[row * 256 + threadIdx.x] = v;  // store mean (for segments)
    __nv_bfloat162* o2 = (__nv_bfloat162*)(g_protoNb + row * D_N);
    o2[2 * threadIdx.x]     = __floats2bfloat162_rn(v.x * inv, v.y * inv);
    o2[2 * threadIdx.x + 1] = __floats2bfloat162_rn(v.z * inv, v.w * inv);
}

// ---------------- 3. prototype segments (padded to 4) -> bf16; grid 256 ----------------
__global__ void proto_seg_kernel() {
    const int b = blockIdx.x;              // k*4 + w
    const int k = b >> 2, w = b & 3;
    __nv_bfloat162* o2 = (__nv_bfloat162*)(g_protoSegNb + b * D_N);
    if (w == 3) {
        const __nv_bfloat162 z = __floats2bfloat162_rn(0.f, 0.f);
        o2[2 * threadIdx.x] = z; o2[2 * threadIdx.x + 1] = z;
        return;
    }
    const float4* base = (const float4*)g_protoSum + (k * T_N + 2 * w) * 256 + threadIdx.x;
    float4 v0 = base[0], v1 = base[256], v2 = base[512], v3 = base[768];
    float4 v = make_float4((v0.x+v1.x+v2.x+v3.x)*0.25f, (v0.y+v1.y+v2.y+v3.y)*0.25f,
                           (v0.z+v1.z+v2.z+v3.z)*0.25f, (v0.w+v1.w+v2.w+v3.w)*0.25f);
    const float ss = blockReduceSum256(v.x*v.x + v.y*v.y + v.z*v.z + v.w*v.w);
    const float inv = 1.f / fmaxf(sqrtf(ss), EPSN);
    o2[2 * threadIdx.x]     = __floats2bfloat162_rn(v.x * inv, v.y * inv);
    o2[2 * threadIdx.x + 1] = __floats2bfloat162_rn(v.z * inv, v.w * inv);
}

// ---------------- 4. target prep: frame norms + segments, fused; grid 4096 ----------------
__global__ void __launch_bounds__(256) tgt_prep_kernel(const float* __restrict__ tgt) {
    __shared__ float sh[T_N * D_N];   // 32 KB
    const int q = blockIdx.x;
    const float4* src = (const float4*)(tgt + (size_t)q * (T_N * D_N));
    float4* dst4 = (float4*)sh;
#pragma unroll
    for (int i = threadIdx.x; i < 2048; i += 256) dst4[i] = src[i];
    __syncthreads();

    const int w = threadIdx.x >> 5, lane = threadIdx.x & 31;

    // frames: warp w handles frame w
    {
        const float* row = sh + w * D_N;
        float ss = 0.f;
#pragma unroll
        for (int jj = 0; jj < 16; ++jj) {
            float2 a = ((const float2*)row)[lane + 32 * jj];
            ss += a.x * a.x + a.y * a.y;
        }
        ss = warpReduceSum(ss);
        const float inv = 1.f / fmaxf(sqrtf(ss), EPSN);
        __nv_bfloat162* o2 = (__nv_bfloat162*)(g_tgtNb + (size_t)(q * T_N + w) * D_N);
#pragma unroll
        for (int jj = 0; jj < 16; ++jj) {
            float2 a = ((const float2*)row)[lane + 32 * jj];
            o2[lane + 32 * jj] = __floats2bfloat162_rn(a.x * inv, a.y * inv);
        }
    }

    // segments: warps 0..2 compute, warp 3 zero pad
    if (w < 4) {
        __nv_bfloat162* o2 = (__nv_bfloat162*)(g_tsegNb + (size_t)(q * 4 + w) * D_N);
        if (w == 3) {
            const __nv_bfloat162 z = __floats2bfloat162_rn(0.f, 0.f);
#pragma unroll
            for (int jj = 0; jj < 16; ++jj) o2[lane + 32 * jj] = z;
        } else {
            const float* r0 = sh + (2 * w) * D_N;  // windows (0,4),(2,6),(4,8)
            float2 seg[16];
            float ss = 0.f;
#pragma unroll
            for (int jj = 0; jj < 16; ++jj) {
                const int j = lane + 32 * jj;
                float2 a = ((const float2*)r0)[j];
                float2 b = ((const float2*)(r0 + D_N))[j];
                float2 c = ((const float2*)(r0 + 2 * D_N))[j];
                float2 d = ((const float2*)(r0 + 3 * D_N))[j];
                float2 m = make_float2((a.x + b.x + c.x + d.x) * 0.25f,
                                       (a.y + b.y + c.y + d.y) * 0.25f);
                seg[jj] = m;
                ss += m.x * m.x + m.y * m.y;
            }
            ss = warpReduceSum(ss);
            const float inv = 1.f / fmaxf(sqrtf(ss), EPSN);
#pragma unroll
            for (int jj = 0; jj < 16; ++jj)
                o2[lane + 32 * jj] = __floats2bfloat162_rn(seg[jj].x * inv, seg[jj].y * inv);
        }
    }
}

// ---------------- 5. bf16 tensor-core GEMM with fused chamfer epilogue ----------------
// Block tile 128x128, 8 warps (4m x 2n), warp tile 32x64, BK=32, 3-stage cp.async.
// Smem tiles use 80-byte row pitch (5 x 16B chunks) -> ldmatrix conflict-free
// without XOR swizzle (row start bank = 20*r mod 32 is a permutation over 8 rows).
#define TILE_BYTES 10240          /* 128 rows * 80 B */
#define STAGE_BYTES 20480         /* A + B */

__device__ __forceinline__ void cp_async16(uint32_t saddr, const void* gptr) {
    asm volatile("cp.async.cg.shared.global [%0], [%1], 16;\n" :: "r"(saddr), "l"(gptr));
}
__device__ __forceinline__ void ldmatrix_x4(uint32_t r[4], uint32_t addr) {
    asm volatile("ldmatrix.sync.aligned.m8n8.x4.shared.b16 {%0,%1,%2,%3}, [%4];\n"
                 : "=r"(r[0]), "=r"(r[1]), "=r"(r[2]), "=r"(r[3]) : "r"(addr));
}
__device__ __forceinline__ void mma16816(float d[4], const uint32_t a[4], uint32_t b0, uint32_t b1) {
    asm volatile("mma.sync.aligned.m16n8k16.row.col.f32.bf16.bf16.f32 "
                 "{%0,%1,%2,%3}, {%4,%5,%6,%7}, {%8,%9}, {%0,%1,%2,%3};\n"
                 : "+f"(d[0]), "+f"(d[1]), "+f"(d[2]), "+f"(d[3])
                 : "r"(a[0]), "r"(a[1]), "r"(a[2]), "r"(a[3]), "r"(b0), "r"(b1));
}

template <bool SEG>
__global__ void __launch_bounds__(256)
mma_gemm_kernel(float* __restrict__ out) {
    extern __shared__ char smem[];
    const __nv_bfloat16* __restrict__ A = SEG ? g_tsegNb : g_tgtNb;
    const __nv_bfloat16* __restrict__ B = SEG ? g_protoSegNb : g_protoNb;

    const int tid = threadIdx.x;
    const int m0 = blockIdx.x * 128;
    const int n0 = blockIdx.y * 128;
    const uint32_t smem_u = (uint32_t)__cvta_generic_to_shared(smem);

    // cp.async assignment: thread -> (row, two 16B chunks)
    const int lrow = tid >> 1;
    const int lchunk = (tid & 1) * 2;
    const __nv_bfloat16* gA = A + (size_t)(m0 + lrow) * D_N + lchunk * 8;
    const __nv_bfloat16* gB = B + (size_t)(n0 + lrow) * D_N + lchunk * 8;
    const uint32_t sA = smem_u + lrow * 80 + lchunk * 16;
    const uint32_t sB = smem_u + TILE_BYTES + lrow * 80 + lchunk * 16;

#define LOAD_STAGE(st, kb) do {                                   \
        const uint32_t _o = (uint32_t)(st) * STAGE_BYTES;         \
        cp_async16(sA + _o,      gA + (kb));                      \
        cp_async16(sA + _o + 16, gA + (kb) + 8);                  \
        cp_async16(sB + _o,      gB + (kb));                      \
        cp_async16(sB + _o + 16, gB + (kb) + 8);                  \
    } while (0)

    // warp tiling
    const int warpId = tid >> 5, lane = tid & 31;
    const int wRow = (warpId & 3) * 32;
    const int wCol = (warpId >> 2) * 64;
    // ldmatrix lane addressing (A: m16k16 frags; B: two n8k16 frags per x4)
    const uint32_t aAddr = smem_u + (uint32_t)(wRow + (lane & 15)) * 80 + (((uint32_t)lane >> 4) << 4);
    const uint32_t bAddr = smem_u + TILE_BYTES
                         + (uint32_t)(wCol + (((lane >> 4) & 1) << 3) + (lane & 7)) * 80
                         + ((((uint32_t)lane >> 3) & 1) << 4);

    float acc[2][8][4];
#pragma unroll
    for (int i = 0; i < 2; ++i)
#pragma unroll
        for (int j = 0; j < 8; ++j)
#pragma unroll
            for (int r = 0; r < 4; ++r) acc[i][j][r] = 0.f;

    LOAD_STAGE(0, 0);
    asm volatile("cp.async.commit_group;\n");
    LOAD_STAGE(1, 32);
    asm volatile("cp.async.commit_group;\n");

    for (int s = 0; s < 32; ++s) {
        if (s + 2 < 32) {
            LOAD_STAGE((s + 2) % 3, (s + 2) * 32);
            asm volatile("cp.async.commit_group;\n");
            asm volatile("cp.async.wait_group 2;\n");
        } else if (s == 30) {
            asm volatile("cp.async.wait_group 1;\n");
        } else {
            asm volatile("cp.async.wait_group 0;\n");
        }
        __syncthreads();

        const uint32_t stOff = (uint32_t)(s % 3) * STAGE_BYTES;
#pragma unroll
        for (int kk = 0; kk < 2; ++kk) {
            uint32_t a[2][4], b[4][4];
#pragma unroll
            for (int mi = 0; mi < 2; ++mi)
                ldmatrix_x4(a[mi], aAddr + stOff + mi * (16 * 80) + kk * 32);
#pragma unroll
            for (int nt = 0; nt < 4; ++nt)
                ldmatrix_x4(b[nt], bAddr + stOff + nt * (16 * 80) + kk * 32);
#pragma unroll
            for (int mi = 0; mi < 2; ++mi)
#pragma unroll
                for (int nj = 0; nj < 8; ++nj)
                    mma16816(acc[mi][nj], a[mi], b[nj >> 1][(nj & 1) * 2], b[nj >> 1][(nj & 1) * 2 + 1]);
        }
        __syncthreads();
    }
#undef LOAD_STAGE

    // ---- epilogue: dump sims to smem (tiles are dead), then chamfer reduce ----
    float* sims = (float*)smem;
#pragma unroll
    for (int mi = 0; mi < 2; ++mi)
#pragma unroll
        for (int nj = 0; nj < 8; ++nj) {
            const int r = wRow + mi * 16 + (lane >> 2);
            const int c = wCol + nj * 8 + (lane & 3) * 2;
            *(float2*)&sims[r * P_SM + c]       = make_float2(acc[mi][nj][0], acc[mi][nj][1]);
            *(float2*)&sims[(r + 8) * P_SM + c] = make_float2(acc[mi][nj][2], acc[mi][nj][3]);
        }
    __syncthreads();

    if (!SEG) {
        // one thread per (q, class): 8x8 block
        const int ql = tid >> 4, cl = tid & 15;
        const float* bp = sims + (ql * 8) * P_SM + cl * 8;
        float cm[8];
#pragma unroll
        for (int j = 0; j < 8; ++j) cm[j] = -1e30f;
        float sRow = 0.f;
#pragma unroll
        for (int i = 0; i < 8; ++i) {
            float rm = -1e30f;
#pragma unroll
            for (int j = 0; j < 8; ++j) {
                const float v = bp[i * P_SM + j];
                rm = fmaxf(rm, v);
                cm[j] = fmaxf(cm[j], v);
            }
            sRow += rm;
        }
        float sCol = 0.f;
#pragma unroll
        for (int j = 0; j < 8; ++j) sCol += cm[j];
        const int q = blockIdx.x * 16 + ql;
        const int c = blockIdx.y * 16 + cl;
        out[QK + q * K_N + c] = sRow + sCol - 16.0f;
    } else {
        // 32q x 32class per block; 4x4 padded blocks, mask to 3x3
#pragma unroll
        for (int p0 = 0; p0 < 4; ++p0) {
            const int p = tid + 256 * p0;
            const int ql = p >> 5, cl = p & 31;
            const float* bp = sims + (ql * 4) * P_SM + cl * 4;
            float cm0 = -1e30f, cm1 = -1e30f, cm2 = -1e30f, sRow = 0.f;
#pragma unroll
            for (int i = 0; i < 3; ++i) {
                const float v0 = bp[i * P_SM + 0];
                const float v1 = bp[i * P_SM + 1];
                const float v2 = bp[i * P_SM + 2];
                sRow += fmaxf(v0, fmaxf(v1, v2));
                cm0 = fmaxf(cm0, v0); cm1 = fmaxf(cm1, v1); cm2 = fmaxf(cm2, v2);
            }
            const float sCol = cm0 + cm1 + cm2;
            const int q = blockIdx.x * 32 + ql;
            const int c = blockIdx.y * 32 + cl;
            out[2 * QK + q * K_N + c] = sCol - 3.0f;   // -seg_s2q
            out[3 * QK + q * K_N + c] = sRow - 3.0f;   // -seg_q2s
        }
    }
}

// ---------------- 6. fusion combine ----------------
__global__ void combine_kernel(const float* __restrict__ ls, const float* __restrict__ fl,
                               float* __restrict__ out) {
    const int i = blockIdx.x * 256 + threadIdx.x;
    const float f0 = fl[0], f1 = fl[1], f2 = fl[2];
    const float mx = fmaxf(f0, fmaxf(f1, f2));
    const float e0 = expf(f0 - mx), e1 = expf(f1 - mx), e2 = expf(f2 - mx);
    const float scale = expf(ls[0]) / (e0 + e1 + e2);
    out[i] = (e0 * out[QK + i] + e1 * out[2 * QK + i] + e2 * out[3 * QK + i]) * scale;
}

// ---------------- launch ----------------
extern "C" void kernel_launch(void* const* d_in, const int* in_sizes, int n_in,
                              void* d_out, int out_size) {
    const float* sup    = (const float*)d_in[0];   // [256,8,1024]
    const float* tgt    = (const float*)d_in[1];   // [4096,8,1024]
    const int*   labels = (const int*)d_in[2];     // [256]
    const float* ls     = (const float*)d_in[3];   // scalar
    const float* fl     = (const float*)d_in[4];   // [3]
    float* out = (float*)d_out;                    // 4 * 4096 * 64

    const int dynSmem = 128 * P_SM * 4;            // 67584 B (>= 3*STAGE_BYTES)
    cudaFuncSetAttribute(mma_gemm_kernel<false>, cudaFuncAttributeMaxDynamicSharedMemorySize, dynSmem);
    cudaFuncSetAttribute(mma_gemm_kernel<true>,  cudaFuncAttributeMaxDynamicSharedMemorySize, dynSmem);

    proto_sum_kernel<<<K_N * 32, 256>>>(sup, labels);
    proto_norm_kernel<<<K_N * T_N, 256>>>();
    proto_seg_kernel<<<K_N * 4, 256>>>();
    tgt_prep_kernel<<<Q_N, 256>>>(tgt);
    mma_gemm_kernel<false><<<dim3(Q_N * T_N / 128, 512 / 128), 256, dynSmem>>>(out);
    mma_gemm_kernel<true><<<dim3(Q_N * 4 / 128, 256 / 128), 256, dynSmem>>>(out);
    combine_kernel<<<QK / 256, 256>>>(ls, fl, out);
}

// round 7
// speedup vs baseline: 10.5181x; 1.0859x over previous
#include <cuda_runtime.h>
#include <cuda_bf16.h>
#include <math.h>
#include <stdint.h>

#define S_N 256
#define Q_N 4096
#define T_N 8
#define D_N 1024
#define K_N 64
#define QK (Q_N * K_N)     /* 262144 */
#define EPSN 1e-12f
#define P_EP 132           /* epilogue buffer row pitch (floats); tile is 128 cols wide! */

// ---------------- scratch (device globals; no allocations allowed) ----------------
__device__ float g_protoSum[K_N * T_N * D_N];   // class sums -> means (in place)
__device__ float g_counts[K_N];
__device__ __align__(16) __nv_bfloat16 g_protoNb[K_N * T_N * D_N];     // normalized prototypes [512][1024]
__device__ __align__(16) __nv_bfloat16 g_protoSegNb[K_N * 4 * D_N];    // normalized seg protos, padded [256][1024]
__device__ __align__(16) __nv_bfloat16 g_tgtNb[Q_N * T_N * D_N];       // normalized target frames [32768][1024]
__device__ __align__(16) __nv_bfloat16 g_tsegNb[Q_N * 4 * D_N];        // normalized target segs, padded [16384][1024]

// ---------------- helpers ----------------
__device__ __forceinline__ float blockReduceSum256(float v) {
    __shared__ float sh[8];
    const int lane = threadIdx.x & 31, wid = threadIdx.x >> 5;
#pragma unroll
    for (int o = 16; o; o >>= 1) v += __shfl_xor_sync(0xffffffffu, v, o);
    if (lane == 0) sh[wid] = v;
    __syncthreads();
    if (wid == 0) {
        float r = (lane < 8) ? sh[lane] : 0.f;
#pragma unroll
        for (int o = 4; o; o >>= 1) r += __shfl_xor_sync(0xffffffffu, r, o);
        if (lane == 0) sh[0] = r;
    }
    __syncthreads();
    return sh[0];
}

__device__ __forceinline__ float warpReduceSum(float v) {
#pragma unroll
    for (int o = 16; o; o >>= 1) v += __shfl_xor_sync(0xffffffffu, v, o);
    return v;
}

// ---------------- 1. per-class sums (deterministic scan, no atomics) ----------------
__global__ void proto_sum_kernel(const float* __restrict__ sup, const int* __restrict__ labels) {
    const int k = blockIdx.x >> 5;
    const int off = (blockIdx.x & 31) * 256 + threadIdx.x;  // 0..8191 within [T*D]
    float acc = 0.f, cnt = 0.f;
    for (int s = 0; s < S_N; ++s) {
        if (labels[s] == k) { acc += sup[s * (T_N * D_N) + off]; cnt += 1.f; }
    }
    g_protoSum[k * (T_N * D_N) + off] = acc;
    if (off == 0) g_counts[k] = cnt;
}

// ---------------- 2. prototype mean + L2 normalize -> bf16; grid 512 ----------------
__global__ void proto_norm_kernel() {
    const int row = blockIdx.x;            // (k*8 + t)
    const int k = row >> 3;
    float4 v = ((const float4*)g_protoSum)[row * 256 + threadIdx.x];
    const float ic = 1.f / g_counts[k];
    v.x *= ic; v.y *= ic; v.z *= ic; v.w *= ic;
    const float ss = blockReduceSum256(v.x*v.x + v.y*v.y + v.z*v.z + v.w*v.w);
    const float inv = 1.f / fmaxf(sqrtf(ss), EPSN);
    ((float4*)g_protoSum)[row * 256 + threadIdx.x] = v;  // store mean (for segments)
    __nv_bfloat162* o2 = (__nv_bfloat162*)(g_protoNb + row * D_N);
    o2[2 * threadIdx.x]     = __floats2bfloat162_rn(v.x * inv, v.y * inv);
    o2[2 * threadIdx.x + 1] = __floats2bfloat162_rn(v.z * inv, v.w * inv);
}

// ---------------- 3. prototype segments (padded to 4) -> bf16; grid 256 ----------------
__global__ void proto_seg_kernel() {
    const int b = blockIdx.x;              // k*4 + w
    const int k = b >> 2, w = b & 3;
    __nv_bfloat162* o2 = (__nv_bfloat162*)(g_protoSegNb + b * D_N);
    if (w == 3) {
        const __nv_bfloat162 z = __floats2bfloat162_rn(0.f, 0.f);
        o2[2 * threadIdx.x] = z; o2[2 * threadIdx.x + 1] = z;
        return;
    }
    const float4* base = (const float4*)g_protoSum + (k * T_N + 2 * w) * 256 + threadIdx.x;
    float4 v0 = base[0], v1 = base[256], v2 = base[512], v3 = base[768];
    float4 v = make_float4((v0.x+v1.x+v2.x+v3.x)*0.25f, (v0.y+v1.y+v2.y+v3.y)*0.25f,
                           (v0.z+v1.z+v2.z+v3.z)*0.25f, (v0.w+v1.w+v2.w+v3.w)*0.25f);
    const float ss = blockReduceSum256(v.x*v.x + v.y*v.y + v.z*v.z + v.w*v.w);
    const float inv = 1.f / fmaxf(sqrtf(ss), EPSN);
    o2[2 * threadIdx.x]     = __floats2bfloat162_rn(v.x * inv, v.y * inv);
    o2[2 * threadIdx.x + 1] = __floats2bfloat162_rn(v.z * inv, v.w * inv);
}

// ---------------- 4. target prep: frame norms + segments, fused; grid 4096 ----------------
__global__ void __launch_bounds__(256) tgt_prep_kernel(const float* __restrict__ tgt) {
    __shared__ float sh[T_N * D_N];   // 32 KB
    const int q = blockIdx.x;
    const float4* src = (const float4*)(tgt + (size_t)q * (T_N * D_N));
    float4* dst4 = (float4*)sh;
#pragma unroll
    for (int i = threadIdx.x; i < 2048; i += 256) dst4[i] = src[i];
    __syncthreads();

    const int w = threadIdx.x >> 5, lane = threadIdx.x & 31;

    // frames: warp w handles frame w
    {
        const float* row = sh + w * D_N;
        float ss = 0.f;
#pragma unroll
        for (int jj = 0; jj < 16; ++jj) {
            float2 a = ((const float2*)row)[lane + 32 * jj];
            ss += a.x * a.x + a.y * a.y;
        }
        ss = warpReduceSum(ss);
        const float inv = 1.f / fmaxf(sqrtf(ss), EPSN);
        __nv_bfloat162* o2 = (__nv_bfloat162*)(g_tgtNb + (size_t)(q * T_N + w) * D_N);
#pragma unroll
        for (int jj = 0; jj < 16; ++jj) {
            float2 a = ((const float2*)row)[lane + 32 * jj];
            o2[lane + 32 * jj] = __floats2bfloat162_rn(a.x * inv, a.y * inv);
        }
    }

    // segments: warps 0..2 compute, warp 3 zero pad
    if (w < 4) {
        __nv_bfloat162* o2 = (__nv_bfloat162*)(g_tsegNb + (size_t)(q * 4 + w) * D_N);
        if (w == 3) {
            const __nv_bfloat162 z = __floats2bfloat162_rn(0.f, 0.f);
#pragma unroll
            for (int jj = 0; jj < 16; ++jj) o2[lane + 32 * jj] = z;
        } else {
            const float* r0 = sh + (2 * w) * D_N;  // windows (0,4),(2,6),(4,8)
            float2 seg[16];
            float ss = 0.f;
#pragma unroll
            for (int jj = 0; jj < 16; ++jj) {
                const int j = lane + 32 * jj;
                float2 a = ((const float2*)r0)[j];
                float2 b = ((const float2*)(r0 + D_N))[j];
                float2 c = ((const float2*)(r0 + 2 * D_N))[j];
                float2 d = ((const float2*)(r0 + 3 * D_N))[j];
                float2 m = make_float2((a.x + b.x + c.x + d.x) * 0.25f,
                                       (a.y + b.y + c.y + d.y) * 0.25f);
                seg[jj] = m;
                ss += m.x * m.x + m.y * m.y;
            }
            ss = warpReduceSum(ss);
            const float inv = 1.f / fmaxf(sqrtf(ss), EPSN);
#pragma unroll
            for (int jj = 0; jj < 16; ++jj)
                o2[lane + 32 * jj] = __floats2bfloat162_rn(seg[jj].x * inv, seg[jj].y * inv);
        }
    }
}

// ---------------- 5. bf16 tensor-core GEMM with fused chamfer epilogue ----------------
// Block tile 128x128, 8 warps (4m x 2n), warp tile 32x64, BK=32, 3-stage cp.async,
// ONE __syncthreads per k-iter. Smem tiles: 80-byte row pitch (conflict-free ldmatrix).
// Epilogue in two mi-rounds through a 64x132 fp32 buffer (33.8 KB over dead tile smem)
// -> dynamic smem = 3 stages only; __launch_bounds__(256,2) -> 2 CTAs/SM.
#define TILE_BYTES 10240          /* 128 rows * 80 B */
#define STAGE_BYTES 20480         /* A + B */

__device__ __forceinline__ void cp_async16(uint32_t saddr, const void* gptr) {
    asm volatile("cp.async.cg.shared.global [%0], [%1], 16;\n" :: "r"(saddr), "l"(gptr));
}
__device__ __forceinline__ void ldmatrix_x4(uint32_t r[4], uint32_t addr) {
    asm volatile("ldmatrix.sync.aligned.m8n8.x4.shared.b16 {%0,%1,%2,%3}, [%4];\n"
                 : "=r"(r[0]), "=r"(r[1]), "=r"(r[2]), "=r"(r[3]) : "r"(addr));
}
__device__ __forceinline__ void mma16816(float d[4], const uint32_t a[4], uint32_t b0, uint32_t b1) {
    asm volatile("mma.sync.aligned.m16n8k16.row.col.f32.bf16.bf16.f32 "
                 "{%0,%1,%2,%3}, {%4,%5,%6,%7}, {%8,%9}, {%0,%1,%2,%3};\n"
                 : "+f"(d[0]), "+f"(d[1]), "+f"(d[2]), "+f"(d[3])
                 : "r"(a[0]), "r"(a[1]), "r"(a[2]), "r"(a[3]), "r"(b0), "r"(b1));
}

template <bool SEG>
__global__ void __launch_bounds__(256, 2)
mma_gemm_kernel(float* __restrict__ out,
                const float* __restrict__ ls, const float* __restrict__ fl) {
    extern __shared__ char smem[];
    const __nv_bfloat16* __restrict__ A = SEG ? g_tsegNb : g_tgtNb;
    const __nv_bfloat16* __restrict__ B = SEG ? g_protoSegNb : g_protoNb;

    const int tid = threadIdx.x;
    const int m0 = blockIdx.x * 128;
    const int n0 = blockIdx.y * 128;
    const uint32_t smem_u = (uint32_t)__cvta_generic_to_shared(smem);

    // cp.async assignment: thread -> (row, two 16B chunks)
    const int lrow = tid >> 1;
    const int lchunk = (tid & 1) * 2;
    const __nv_bfloat16* gA = A + (size_t)(m0 + lrow) * D_N + lchunk * 8;
    const __nv_bfloat16* gB = B + (size_t)(n0 + lrow) * D_N + lchunk * 8;
    const uint32_t sA = smem_u + lrow * 80 + lchunk * 16;
    const uint32_t sB = smem_u + TILE_BYTES + lrow * 80 + lchunk * 16;

#define LOAD_STAGE(st, kb) do {                                   \
        const uint32_t _o = (uint32_t)(st) * STAGE_BYTES;         \
        cp_async16(sA + _o,      gA + (kb));                      \
        cp_async16(sA + _o + 16, gA + (kb) + 8);                  \
        cp_async16(sB + _o,      gB + (kb));                      \
        cp_async16(sB + _o + 16, gB + (kb) + 8);                  \
    } while (0)

    // warp tiling
    const int warpId = tid >> 5, lane = tid & 31;
    const int wm = warpId & 3;
    const int wRow = wm * 32;
    const int wCol = (warpId >> 2) * 64;
    // ldmatrix lane addressing (A: m16k16 frags; B: two n8k16 frags per x4)
    const uint32_t aAddr = smem_u + (uint32_t)(wRow + (lane & 15)) * 80 + (((uint32_t)lane >> 4) << 4);
    const uint32_t bAddr = smem_u + TILE_BYTES
                         + (uint32_t)(wCol + (((lane >> 4) & 1) << 3) + (lane & 7)) * 80
                         + ((((uint32_t)lane >> 3) & 1) << 4);

    float acc[2][8][4];
#pragma unroll
    for (int i = 0; i < 2; ++i)
#pragma unroll
        for (int j = 0; j < 8; ++j)
#pragma unroll
            for (int r = 0; r < 4; ++r) acc[i][j][r] = 0.f;

    LOAD_STAGE(0, 0);
    asm volatile("cp.async.commit_group;\n");
    LOAD_STAGE(1, 32);
    asm volatile("cp.async.commit_group;\n");

    for (int s = 0; s < 32; ++s) {
        if (s < 31) asm volatile("cp.async.wait_group 1;\n");
        else        asm volatile("cp.async.wait_group 0;\n");
        __syncthreads();   // stage s ready for all; stage (s+2)%3 == (s-1)%3 free to overwrite

        if (s + 2 < 32) {
            LOAD_STAGE((s + 2) % 3, (s + 2) * 32);
            asm volatile("cp.async.commit_group;\n");
        }

        const uint32_t stOff = (uint32_t)(s % 3) * STAGE_BYTES;
#pragma unroll
        for (int kk = 0; kk < 2; ++kk) {
            uint32_t a[2][4], b[4][4];
#pragma unroll
            for (int mi = 0; mi < 2; ++mi)
                ldmatrix_x4(a[mi], aAddr + stOff + mi * (16 * 80) + kk * 32);
#pragma unroll
            for (int nt = 0; nt < 4; ++nt)
                ldmatrix_x4(b[nt], bAddr + stOff + nt * (16 * 80) + kk * 32);
#pragma unroll
            for (int mi = 0; mi < 2; ++mi)
#pragma unroll
                for (int nj = 0; nj < 8; ++nj)
                    mma16816(acc[mi][nj], a[mi], b[nj >> 1][(nj & 1) * 2], b[nj >> 1][(nj & 1) * 2 + 1]);
        }
    }
#undef LOAD_STAGE

    // ---- epilogue: two rounds (mi=0,1), 64x132 fp32 buffer over dead tile smem ----
    float* buf = (float*)smem;
    // softmax fusion weights (only needed for SEG fused write)
    float e0 = 0.f, e1 = 0.f, e2 = 0.f;
    if (SEG) {
        const float f0 = fl[0], f1 = fl[1], f2 = fl[2];
        const float mx = fmaxf(f0, fmaxf(f1, f2));
        e0 = expf(f0 - mx); e1 = expf(f1 - mx); e2 = expf(f2 - mx);
        const float sc = expf(ls[0]) / (e0 + e1 + e2);
        e0 *= sc; e1 *= sc; e2 *= sc;
    }

#pragma unroll
    for (int mi = 0; mi < 2; ++mi) {
        __syncthreads();   // previous round reads (or mainloop) done
        {
            const int cr0 = wm * 16 + (lane >> 2);
#pragma unroll
            for (int nj = 0; nj < 8; ++nj) {
                const int c = wCol + nj * 8 + (lane & 3) * 2;
                *(float2*)&buf[cr0 * P_EP + c]       = make_float2(acc[mi][nj][0], acc[mi][nj][1]);
                *(float2*)&buf[(cr0 + 8) * P_EP + c] = make_float2(acc[mi][nj][2], acc[mi][nj][3]);
            }
        }
        __syncthreads();

        if (!SEG) {
            // 128 pairs per round: g in [0,8) (8-row group), c in [0,16)
            if (tid < 128) {
                const int g = tid >> 4, c = tid & 15;
                const float* bp = buf + (g * 8) * P_EP + c * 8;
                float cm[8];
#pragma unroll
                for (int j = 0; j < 8; ++j) cm[j] = -1e30f;
                float sRow = 0.f;
#pragma unroll
                for (int i = 0; i < 8; ++i) {
                    float rm = -1e30f;
#pragma unroll
                    for (int j = 0; j < 8; ++j) {
                        const float v = bp[i * P_EP + j];
                        rm = fmaxf(rm, v);
                        cm[j] = fmaxf(cm[j], v);
                    }
                    sRow += rm;
                }
                float sCol = 0.f;
#pragma unroll
                for (int j = 0; j < 8; ++j) sCol += cm[j];
                const int q = (m0 >> 3) + (g >> 1) * 4 + mi * 2 + (g & 1);
                const int cc = (n0 >> 3) + c;
                out[QK + q * K_N + cc] = sRow + sCol - 16.0f;
            }
        } else {
            // 512 pairs per round: qg in [0,16) (4-row group), c in [0,32); 2 per thread
#pragma unroll
            for (int p0 = 0; p0 < 2; ++p0) {
                const int p = tid + 256 * p0;
                const int qg = p >> 5, c = p & 31;
                const float* bp = buf + (qg * 4) * P_EP + c * 4;
                float cm0 = -1e30f, cm1 = -1e30f, cm2 = -1e30f, sRow = 0.f;
#pragma unroll
                for (int i = 0; i < 3; ++i) {
                    const float v0 = bp[i * P_EP + 0];
                    const float v1 = bp[i * P_EP + 1];
                    const float v2 = bp[i * P_EP + 2];
                    sRow += fmaxf(v0, fmaxf(v1, v2));
                    cm0 = fmaxf(cm0, v0); cm1 = fmaxf(cm1, v1); cm2 = fmaxf(cm2, v2);
                }
                const float sCol = cm0 + cm1 + cm2;
                const int q = (m0 >> 2) + (qg >> 2) * 8 + mi * 4 + (qg & 3);
                const int cc = (n0 >> 2) + c;
                const int idx = q * K_N + cc;
                const float s2q = sCol - 3.0f;   // -seg_s2q
                const float q2s = sRow - 3.0f;   // -seg_q2s
                out[2 * QK + idx] = s2q;
                out[3 * QK + idx] = q2s;
                // fused output (main gemm already wrote -global at QK+idx)
                out[idx] = e0 * out[QK + idx] + e1 * s2q + e2 * q2s;
            }
        }
    }
}

// ---------------- launch ----------------
extern "C" void kernel_launch(void* const* d_in, const int* in_sizes, int n_in,
                              void* d_out, int out_size) {
    const float* sup    = (const float*)d_in[0];   // [256,8,1024]
    const float* tgt    = (const float*)d_in[1];   // [4096,8,1024]
    const int*   labels = (const int*)d_in[2];     // [256]
    const float* ls     = (const float*)d_in[3];   // scalar
    const float* fl     = (const float*)d_in[4];   // [3]
    float* out = (float*)d_out;                    // 4 * 4096 * 64

    const int dynSmem = 3 * STAGE_BYTES;           // 61440 B (>= 64*P_EP*4 = 33792)
    cudaFuncSetAttribute(mma_gemm_kernel<false>, cudaFuncAttributeMaxDynamicSharedMemorySize, dynSmem);
    cudaFuncSetAttribute(mma_gemm_kernel<true>,  cudaFuncAttributeMaxDynamicSharedMemorySize, dynSmem);

    proto_sum_kernel<<<K_N * 32, 256>>>(sup, labels);
    proto_norm_kernel<<<K_N * T_N, 256>>>();
    proto_seg_kernel<<<K_N * 4, 256>>>();
    tgt_prep_kernel<<<Q_N, 256>>>(tgt);
    mma_gemm_kernel<false><<<dim3(Q_N * T_N / 128, 512 / 128), 256, dynSmem>>>(out, ls, fl);
    mma_gemm_kernel<true><<<dim3(Q_N * 4 / 128, 256 / 128), 256, dynSmem>>>(out, ls, fl);
}

// round 8
// speedup vs baseline: 11.7904x; 1.1210x over previous
#include <cuda_runtime.h>
#include <cuda_bf16.h>
#include <math.h>
#include <stdint.h>

#define S_N 256
#define Q_N 4096
#define T_N 8
#define D_N 1024
#define K_N 64
#define QK (Q_N * K_N)     /* 262144 */
#define EPSN 1e-12f
#define P_EP 132           /* epilogue buffer row pitch (floats); tile is 128 cols wide! */

// ---------------- scratch (device globals; no allocations allowed) ----------------
__device__ float g_protoSum[K_N * T_N * D_N];   // class means (fp32, for segments)
__device__ int g_members[K_N * S_N];            // per-class member indices (ascending)
__device__ int g_mcount[K_N];
__device__ __align__(16) __nv_bfloat16 g_protoNb[K_N * T_N * D_N];     // normalized prototypes [512][1024]
__device__ __align__(16) __nv_bfloat16 g_protoSegNb[K_N * 4 * D_N];    // normalized seg protos, padded [256][1024]
__device__ __align__(16) __nv_bfloat16 g_tgtNb[Q_N * T_N * D_N];       // normalized target frames [32768][1024]
__device__ __align__(16) __nv_bfloat16 g_tsegNb[Q_N * 4 * D_N];        // normalized target segs, padded [16384][1024]

// ---------------- helpers ----------------
__device__ __forceinline__ float blockReduceSum256(float v) {
    __shared__ float sh[8];
    const int lane = threadIdx.x & 31, wid = threadIdx.x >> 5;
#pragma unroll
    for (int o = 16; o; o >>= 1) v += __shfl_xor_sync(0xffffffffu, v, o);
    if (lane == 0) sh[wid] = v;
    __syncthreads();
    if (wid == 0) {
        float r = (lane < 8) ? sh[lane] : 0.f;
#pragma unroll
        for (int o = 4; o; o >>= 1) r += __shfl_xor_sync(0xffffffffu, r, o);
        if (lane == 0) sh[0] = r;
    }
    __syncthreads();
    return sh[0];
}

__device__ __forceinline__ float warpReduceSum(float v) {
#pragma unroll
    for (int o = 16; o; o >>= 1) v += __shfl_xor_sync(0xffffffffu, v, o);
    return v;
}

// ---------------- 0. per-class member lists (deterministic, ascending s) ----------------
__global__ void build_members_kernel(const int* __restrict__ labels) {
    const int k = threadIdx.x;             // 64 threads
    int cnt = 0;
    for (int s = 0; s < S_N; ++s)
        if (labels[s] == k) g_members[k * S_N + cnt++] = s;
    g_mcount[k] = cnt;
}

// ---------------- 1+2. prototype mean + L2 normalize -> bf16; grid 512 (k,t) ----------------
// Reads only the class's member rows (8 MB total vs 536 MB for full scan).
__global__ void proto_mean_norm_kernel(const float* __restrict__ sup) {
    const int row = blockIdx.x;            // (k*8 + t)
    const int k = row >> 3, t = row & 7;
    const int cnt = g_mcount[k];
    float4 v = make_float4(0.f, 0.f, 0.f, 0.f);
    for (int i = 0; i < cnt; ++i) {        // ascending s: same fp32 order as before
        const int s = g_members[k * S_N + i];
        float4 a = ((const float4*)(sup + ((size_t)s * T_N + t) * D_N))[threadIdx.x];
        v.x += a.x; v.y += a.y; v.z += a.z; v.w += a.w;
    }
    const float ic = 1.f / (float)cnt;
    v.x *= ic; v.y *= ic; v.z *= ic; v.w *= ic;
    const float ss = blockReduceSum256(v.x*v.x + v.y*v.y + v.z*v.z + v.w*v.w);
    const float inv = 1.f / fmaxf(sqrtf(ss), EPSN);
    ((float4*)g_protoSum)[row * 256 + threadIdx.x] = v;  // store mean (for segments)
    __nv_bfloat162* o2 = (__nv_bfloat162*)(g_protoNb + row * D_N);
    o2[2 * threadIdx.x]     = __floats2bfloat162_rn(v.x * inv, v.y * inv);
    o2[2 * threadIdx.x + 1] = __floats2bfloat162_rn(v.z * inv, v.w * inv);
}

// ---------------- 3. prototype segments (padded to 4) -> bf16; grid 256 ----------------
__global__ void proto_seg_kernel() {
    const int b = blockIdx.x;              // k*4 + w
    const int k = b >> 2, w = b & 3;
    __nv_bfloat162* o2 = (__nv_bfloat162*)(g_protoSegNb + b * D_N);
    if (w == 3) {
        const __nv_bfloat162 z = __floats2bfloat162_rn(0.f, 0.f);
        o2[2 * threadIdx.x] = z; o2[2 * threadIdx.x + 1] = z;
        return;
    }
    const float4* base = (const float4*)g_protoSum + (k * T_N + 2 * w) * 256 + threadIdx.x;
    float4 v0 = base[0], v1 = base[256], v2 = base[512], v3 = base[768];
    float4 v = make_float4((v0.x+v1.x+v2.x+v3.x)*0.25f, (v0.y+v1.y+v2.y+v3.y)*0.25f,
                           (v0.z+v1.z+v2.z+v3.z)*0.25f, (v0.w+v1.w+v2.w+v3.w)*0.25f);
    const float ss = blockReduceSum256(v.x*v.x + v.y*v.y + v.z*v.z + v.w*v.w);
    const float inv = 1.f / fmaxf(sqrtf(ss), EPSN);
    o2[2 * threadIdx.x]     = __floats2bfloat162_rn(v.x * inv, v.y * inv);
    o2[2 * threadIdx.x + 1] = __floats2bfloat162_rn(v.z * inv, v.w * inv);
}

// ---------------- 4. target prep: frame norms + segments, fused; grid 4096 ----------------
__global__ void __launch_bounds__(256) tgt_prep_kernel(const float* __restrict__ tgt) {
    __shared__ float sh[T_N * D_N];   // 32 KB
    const int q = blockIdx.x;
    const float4* src = (const float4*)(tgt + (size_t)q * (T_N * D_N));
    float4* dst4 = (float4*)sh;
#pragma unroll
    for (int i = threadIdx.x; i < 2048; i += 256) dst4[i] = src[i];
    __syncthreads();

    const int w = threadIdx.x >> 5, lane = threadIdx.x & 31;

    // frames: warp w handles frame w
    {
        const float* row = sh + w * D_N;
        float ss = 0.f;
#pragma unroll
        for (int jj = 0; jj < 16; ++jj) {
            float2 a = ((const float2*)row)[lane + 32 * jj];
            ss += a.x * a.x + a.y * a.y;
        }
        ss = warpReduceSum(ss);
        const float inv = 1.f / fmaxf(sqrtf(ss), EPSN);
        __nv_bfloat162* o2 = (__nv_bfloat162*)(g_tgtNb + (size_t)(q * T_N + w) * D_N);
#pragma unroll
        for (int jj = 0; jj < 16; ++jj) {
            float2 a = ((const float2*)row)[lane + 32 * jj];
            o2[lane + 32 * jj] = __floats2bfloat162_rn(a.x * inv, a.y * inv);
        }
    }

    // segments: warps 0..2 compute, warp 3 zero pad
    if (w < 4) {
        __nv_bfloat162* o2 = (__nv_bfloat162*)(g_tsegNb + (size_t)(q * 4 + w) * D_N);
        if (w == 3) {
            const __nv_bfloat162 z = __floats2bfloat162_rn(0.f, 0.f);
#pragma unroll
            for (int jj = 0; jj < 16; ++jj) o2[lane + 32 * jj] = z;
        } else {
            const float* r0 = sh + (2 * w) * D_N;  // windows (0,4),(2,6),(4,8)
            float2 seg[16];
            float ss = 0.f;
#pragma unroll
            for (int jj = 0; jj < 16; ++jj) {
                const int j = lane + 32 * jj;
                float2 a = ((const float2*)r0)[j];
                float2 b = ((const float2*)(r0 + D_N))[j];
                float2 c = ((const float2*)(r0 + 2 * D_N))[j];
                float2 d = ((const float2*)(r0 + 3 * D_N))[j];
                float2 m = make_float2((a.x + b.x + c.x + d.x) * 0.25f,
                                       (a.y + b.y + c.y + d.y) * 0.25f);
                seg[jj] = m;
                ss += m.x * m.x + m.y * m.y;
            }
            ss = warpReduceSum(ss);
            const float inv = 1.f / fmaxf(sqrtf(ss), EPSN);
#pragma unroll
            for (int jj = 0; jj < 16; ++jj)
                o2[lane + 32 * jj] = __floats2bfloat162_rn(seg[jj].x * inv, seg[jj].y * inv);
        }
    }
}

// ---------------- 5. bf16 tensor-core GEMM with fused chamfer epilogue ----------------
// Block tile 128x128, 8 warps (4m x 2n), warp tile 32x64, BK=32, 3-stage cp.async,
// ONE __syncthreads per k-iter. Smem tiles: 80-byte row pitch (conflict-free ldmatrix).
// Epilogue in two mi-rounds through a 64x132 fp32 buffer (33.8 KB over dead tile smem)
// -> dynamic smem = 3 stages only; __launch_bounds__(256,2) -> 2 CTAs/SM.
#define TILE_BYTES 10240          /* 128 rows * 80 B */
#define STAGE_BYTES 20480         /* A + B */

__device__ __forceinline__ void cp_async16(uint32_t saddr, const void* gptr) {
    asm volatile("cp.async.cg.shared.global [%0], [%1], 16;\n" :: "r"(saddr), "l"(gptr));
}
__device__ __forceinline__ void ldmatrix_x4(uint32_t r[4], uint32_t addr) {
    asm volatile("ldmatrix.sync.aligned.m8n8.x4.shared.b16 {%0,%1,%2,%3}, [%4];\n"
                 : "=r"(r[0]), "=r"(r[1]), "=r"(r[2]), "=r"(r[3]) : "r"(addr));
}
__device__ __forceinline__ void mma16816(float d[4], const uint32_t a[4], uint32_t b0, uint32_t b1) {
    asm volatile("mma.sync.aligned.m16n8k16.row.col.f32.bf16.bf16.f32 "
                 "{%0,%1,%2,%3}, {%4,%5,%6,%7}, {%8,%9}, {%0,%1,%2,%3};\n"
                 : "+f"(d[0]), "+f"(d[1]), "+f"(d[2]), "+f"(d[3])
                 : "r"(a[0]), "r"(a[1]), "r"(a[2]), "r"(a[3]), "r"(b0), "r"(b1));
}

template <bool SEG>
__global__ void __launch_bounds__(256, 2)
mma_gemm_kernel(float* __restrict__ out,
                const float* __restrict__ ls, const float* __restrict__ fl) {
    extern __shared__ char smem[];
    const __nv_bfloat16* __restrict__ A = SEG ? g_tsegNb : g_tgtNb;
    const __nv_bfloat16* __restrict__ B = SEG ? g_protoSegNb : g_protoNb;

    const int tid = threadIdx.x;
    const int m0 = blockIdx.x * 128;
    const int n0 = blockIdx.y * 128;
    const uint32_t smem_u = (uint32_t)__cvta_generic_to_shared(smem);

    // cp.async assignment: thread -> (row, two 16B chunks)
    const int lrow = tid >> 1;
    const int lchunk = (tid & 1) * 2;
    const __nv_bfloat16* gA = A + (size_t)(m0 + lrow) * D_N + lchunk * 8;
    const __nv_bfloat16* gB = B + (size_t)(n0 + lrow) * D_N + lchunk * 8;
    const uint32_t sA = smem_u + lrow * 80 + lchunk * 16;
    const uint32_t sB = smem_u + TILE_BYTES + lrow * 80 + lchunk * 16;

#define LOAD_STAGE(st, kb) do {                                   \
        const uint32_t _o = (uint32_t)(st) * STAGE_BYTES;         \
        cp_async16(sA + _o,      gA + (kb));                      \
        cp_async16(sA + _o + 16, gA + (kb) + 8);                  \
        cp_async16(sB + _o,      gB + (kb));                      \
        cp_async16(sB + _o + 16, gB + (kb) + 8);                  \
    } while (0)

    // warp tiling
    const int warpId = tid >> 5, lane = tid & 31;
    const int wm = warpId & 3;
    const int wRow = wm * 32;
    const int wCol = (warpId >> 2) * 64;
    // ldmatrix lane addressing (A: m16k16 frags; B: two n8k16 frags per x4)
    const uint32_t aAddr = smem_u + (uint32_t)(wRow + (lane & 15)) * 80 + (((uint32_t)lane >> 4) << 4);
    const uint32_t bAddr = smem_u + TILE_BYTES
                         + (uint32_t)(wCol + (((lane >> 4) & 1) << 3) + (lane & 7)) * 80
                         + ((((uint32_t)lane >> 3) & 1) << 4);

    float acc[2][8][4];
#pragma unroll
    for (int i = 0; i < 2; ++i)
#pragma unroll
        for (int j = 0; j < 8; ++j)
#pragma unroll
            for (int r = 0; r < 4; ++r) acc[i][j][r] = 0.f;

    LOAD_STAGE(0, 0);
    asm volatile("cp.async.commit_group;\n");
    LOAD_STAGE(1, 32);
    asm volatile("cp.async.commit_group;\n");

    for (int s = 0; s < 32; ++s) {
        if (s < 31) asm volatile("cp.async.wait_group 1;\n");
        else        asm volatile("cp.async.wait_group 0;\n");
        __syncthreads();   // stage s ready for all; stage (s+2)%3 == (s-1)%3 free to overwrite

        if (s + 2 < 32) {
            LOAD_STAGE((s + 2) % 3, (s + 2) * 32);
            asm volatile("cp.async.commit_group;\n");
        }

        const uint32_t stOff = (uint32_t)(s % 3) * STAGE_BYTES;
#pragma unroll
        for (int kk = 0; kk < 2; ++kk) {
            uint32_t a[2][4], b[4][4];
#pragma unroll
            for (int mi = 0; mi < 2; ++mi)
                ldmatrix_x4(a[mi], aAddr + stOff + mi * (16 * 80) + kk * 32);
#pragma unroll
            for (int nt = 0; nt < 4; ++nt)
                ldmatrix_x4(b[nt], bAddr + stOff + nt * (16 * 80) + kk * 32);
#pragma unroll
            for (int mi = 0; mi < 2; ++mi)
#pragma unroll
                for (int nj = 0; nj < 8; ++nj)
                    mma16816(acc[mi][nj], a[mi], b[nj >> 1][(nj & 1) * 2], b[nj >> 1][(nj & 1) * 2 + 1]);
        }
    }
#undef LOAD_STAGE

    // ---- epilogue: two rounds (mi=0,1), 64x132 fp32 buffer over dead tile smem ----
    float* buf = (float*)smem;
    // softmax fusion weights (only needed for SEG fused write)
    float e0 = 0.f, e1 = 0.f, e2 = 0.f;
    if (SEG) {
        const float f0 = fl[0], f1 = fl[1], f2 = fl[2];
        const float mx = fmaxf(f0, fmaxf(f1, f2));
        e0 = expf(f0 - mx); e1 = expf(f1 - mx); e2 = expf(f2 - mx);
        const float sc = expf(ls[0]) / (e0 + e1 + e2);
        e0 *= sc; e1 *= sc; e2 *= sc;
    }

#pragma unroll
    for (int mi = 0; mi < 2; ++mi) {
        __syncthreads();   // previous round reads (or mainloop) done
        {
            const int cr0 = wm * 16 + (lane >> 2);
#pragma unroll
            for (int nj = 0; nj < 8; ++nj) {
                const int c = wCol + nj * 8 + (lane & 3) * 2;
                *(float2*)&buf[cr0 * P_EP + c]       = make_float2(acc[mi][nj][0], acc[mi][nj][1]);
                *(float2*)&buf[(cr0 + 8) * P_EP + c] = make_float2(acc[mi][nj][2], acc[mi][nj][3]);
            }
        }
        __syncthreads();

        if (!SEG) {
            // 128 pairs per round: g in [0,8) (8-row group), c in [0,16)
            if (tid < 128) {
                const int g = tid >> 4, c = tid & 15;
                const float* bp = buf + (g * 8) * P_EP + c * 8;
                float cm[8];
#pragma unroll
                for (int j = 0; j < 8; ++j) cm[j] = -1e30f;
                float sRow = 0.f;
#pragma unroll
                for (int i = 0; i < 8; ++i) {
                    float rm = -1e30f;
#pragma unroll
                    for (int j = 0; j < 8; ++j) {
                        const float v = bp[i * P_EP + j];
                        rm = fmaxf(rm, v);
                        cm[j] = fmaxf(cm[j], v);
                    }
                    sRow += rm;
                }
                float sCol = 0.f;
#pragma unroll
                for (int j = 0; j < 8; ++j) sCol += cm[j];
                const int q = (m0 >> 3) + (g >> 1) * 4 + mi * 2 + (g & 1);
                const int cc = (n0 >> 3) + c;
                out[QK + q * K_N + cc] = sRow + sCol - 16.0f;
            }
        } else {
            // 512 pairs per round: qg in [0,16) (4-row group), c in [0,32); 2 per thread
#pragma unroll
            for (int p0 = 0; p0 < 2; ++p0) {
                const int p = tid + 256 * p0;
                const int qg = p >> 5, c = p & 31;
                const float* bp = buf + (qg * 4) * P_EP + c * 4;
                float cm0 = -1e30f, cm1 = -1e30f, cm2 = -1e30f, sRow = 0.f;
#pragma unroll
                for (int i = 0; i < 3; ++i) {
                    const float v0 = bp[i * P_EP + 0];
                    const float v1 = bp[i * P_EP + 1];
                    const float v2 = bp[i * P_EP + 2];
                    sRow += fmaxf(v0, fmaxf(v1, v2));
                    cm0 = fmaxf(cm0, v0); cm1 = fmaxf(cm1, v1); cm2 = fmaxf(cm2, v2);
                }
                const float sCol = cm0 + cm1 + cm2;
                const int q = (m0 >> 2) + (qg >> 2) * 8 + mi * 4 + (qg & 3);
                const int cc = (n0 >> 2) + c;
                const int idx = q * K_N + cc;
                const float s2q = sCol - 3.0f;   // -seg_s2q
                const float q2s = sRow - 3.0f;   // -seg_q2s
                out[2 * QK + idx] = s2q;
                out[3 * QK + idx] = q2s;
                // fused output (main gemm already wrote -global at QK+idx)
                out[idx] = e0 * out[QK + idx] + e1 * s2q + e2 * q2s;
            }
        }
    }
}

// ---------------- launch ----------------
extern "C" void kernel_launch(void* const* d_in, const int* in_sizes, int n_in,
                              void* d_out, int out_size) {
    const float* sup    = (const float*)d_in[0];   // [256,8,1024]
    const float* tgt    = (const float*)d_in[1];   // [4096,8,1024]
    const int*   labels = (const int*)d_in[2];     // [256]
    const float* ls     = (const float*)d_in[3];   // scalar
    const float* fl     = (const float*)d_in[4];   // [3]
    float* out = (float*)d_out;                    // 4 * 4096 * 64

    const int dynSmem = 3 * STAGE_BYTES;           // 61440 B (>= 64*P_EP*4 = 33792)
    cudaFuncSetAttribute(mma_gemm_kernel<false>, cudaFuncAttributeMaxDynamicSharedMemorySize, dynSmem);
    cudaFuncSetAttribute(mma_gemm_kernel<true>,  cudaFuncAttributeMaxDynamicSharedMemorySize, dynSmem);

    build_members_kernel<<<1, 64>>>(labels);
    proto_mean_norm_kernel<<<K_N * T_N, 256>>>(sup);
    proto_seg_kernel<<<K_N * 4, 256>>>();
    tgt_prep_kernel<<<Q_N, 256>>>(tgt);
    mma_gemm_kernel<false><<<dim3(Q_N * T_N / 128, 512 / 128), 256, dynSmem>>>(out, ls, fl);
    mma_gemm_kernel<true><<<dim3(Q_N * 4 / 128, 256 / 128), 256, dynSmem>>>(out, ls, fl);
}